// round 12
// baseline (speedup 1.0000x reference)
#include <cuda_runtime.h>

#define R_ 8
#define K_ 10
#define D_ 256
#define DL_ 10
#define B_ 4096
#define MT 64
#define NT_ 64          // number of row tiles = B_/MT
#define ZSTR 132        // 132 mod 32 = 4 -> conflict-friendly; k-slots of 12 floats

// ---------------- device scratch (static, no allocs) ----------------
__device__ float    g_P[R_ * K_ * 56];                 // packed symmetric Gram
__device__ unsigned g_xp[NT_ * 16 * 4 * 64 * 4];       // x tf32 frag-order [tile][kb][tig][row]{4k}  (4MB)
__device__ unsigned g_u1[R_ * 13 * 16 * 32 * 4];       // GEMM1 B frags [r][tile13][kb16][lane]{4k}   (1MB)
__device__ unsigned g_u2[R_ * 32 * 7 * 32 * 4];        // GEMM2 B frags [r][tileN32][kb7][lane]{4j}   (0.9MB)

__device__ __forceinline__ unsigned tf32b(float f) {
    unsigned u;
    asm("cvt.rna.tf32.f32 %0, %1;" : "=r"(u) : "f"(f));
    return u;
}
__device__ __forceinline__ unsigned smem_u32(const void* p) {
    unsigned a;
    asm("{ .reg .u64 t; cvta.to.shared.u64 t, %1; cvt.u32.u64 %0, t; }" : "=r"(a) : "l"(p));
    return a;
}
__device__ __forceinline__ void mma8(float* c, unsigned a0, unsigned a1,
                                     unsigned a2, unsigned a3,
                                     unsigned b0, unsigned b1) {
    asm volatile(
        "mma.sync.aligned.m16n8k8.row.col.f32.tf32.tf32.f32 "
        "{%0,%1,%2,%3}, {%4,%5,%6,%7}, {%8,%9}, {%0,%1,%2,%3};"
        : "+f"(c[0]), "+f"(c[1]), "+f"(c[2]), "+f"(c[3])
        : "r"(a0), "r"(a1), "r"(a2), "r"(a3), "r"(b0), "r"(b1));
}
#define CP16(dst, src) \
    asm volatile("cp.async.cg.shared.global [%0], [%1], 16;" :: "r"(dst), "l"(src) : "memory")
#define CPCOMMIT() asm volatile("cp.async.commit_group;" ::: "memory")
#define CPWAIT2()  asm volatile("cp.async.wait_group 2;" ::: "memory")

// ---------------- fused prep kernel ----------------
// blocks [0,256):   xpack  tile = b>>2, quarter = b&3
// blocks [256,336): gram   rk   = b-256
// blocks [336,440): upack1 idx  = b-336  (r*13+tile)
// blocks [440,696): upack2 idx  = b-440  (r*32+tile)
__global__ void __launch_bounds__(256)
ks_prep(const float* __restrict__ x, const float* __restrict__ Us) {
    const int b = blockIdx.x, tidb = threadIdx.x;

    if (b < 256) {                      // ---- xpack (quarter tiles) ----
        const int tile = b >> 2, q = b & 3;
        #pragma unroll
        for (int it = 0; it < 4; it++) {
            const int e = q * 1024 + it * 256 + tidb;
            const int row = e & 63, kt = e >> 6;
            const int k0 = (kt >> 2) * 16 + (kt & 3) * 4;
            const float* xp = x + (size_t)(tile * 64 + row) * D_ + k0;
            uint4 v;
            v.x = tf32b(xp[0]); v.y = tf32b(xp[1]);
            v.z = tf32b(xp[2]); v.w = tf32b(xp[3]);
            ((uint4*)g_xp)[(size_t)tile * 4096 + e] = v;
        }
    } else if (b < 336) {               // ---- gram ----
        __shared__ float u[D_ * DL_];
        __shared__ float G[DL_ * DL_];
        const int rk = b - 256;
        const float* Up = Us + (size_t)rk * D_ * DL_;
        for (int i = tidb; i < D_ * DL_; i += 256) u[i] = Up[i];
        __syncthreads();
        if (tidb < DL_ * DL_) {
            const int i = tidb / DL_, j = tidb % DL_;
            float s = 0.0f;
            #pragma unroll 8
            for (int dd = 0; dd < D_; dd++) s += u[dd * DL_ + i] * u[dd * DL_ + j];
            G[tidb] = s;
        }
        __syncthreads();
        if (tidb < 55) {
            int tt = tidb, i = 0;
            while (tt >= DL_ - i) { tt -= DL_ - i; i++; }
            const int j = i + tt;
            g_P[rk * 56 + tidb] = G[i * DL_ + j] * (i == j ? 1.0f : 2.0f);
        }
    } else if (b < 440) {               // ---- upack1 ----
        const int idx = b - 336;
        const int r = idx / 13, tile = idx % 13;
        for (int e = tidb; e < 512; e += 256) {
            const int lane = e & 31, kb = e >> 5;
            const int g = lane >> 2, tig = lane & 3;
            const int j = tile * 8 + g, k0 = kb * 16 + tig * 4;
            uint4 v = make_uint4(0u, 0u, 0u, 0u);
            if (j < 100) {
                const float* up = Us + ((size_t)(r * 10 + j / 10) * D_ + k0) * 10 + (j % 10);
                v.x = tf32b(up[0]);  v.y = tf32b(up[10]);
                v.z = tf32b(up[20]); v.w = tf32b(up[30]);
            }
            ((uint4*)g_u1)[((r * 13 + tile) * 16 + kb) * 32 + lane] = v;
        }
    } else {                            // ---- upack2 ----
        const int idx = b - 440;
        const int r = idx >> 5, tile = idx & 31;
        if (tidb < 224) {
            const int lane = tidb & 31, kb = tidb >> 5;
            const int g = lane >> 2, tig = lane & 3;
            const int dd = tile * 8 + g, j0 = kb * 16 + tig * 4;
            unsigned w[4];
            #pragma unroll
            for (int q = 0; q < 4; q++) {
                const int j = j0 + q;
                w[q] = (j < 100)
                    ? tf32b(Us[((size_t)(r * 10 + j / 10) * D_ + dd) * 10 + (j % 10)])
                    : 0u;
            }
            ((uint4*)g_u2)[((r * 32 + tile) * 7 + kb) * 32 + lane] =
                make_uint4(w[0], w[1], w[2], w[3]);
        }
    }
}

// ---------------- smem layout (bytes) ----------------
#define SM_W    0          // 64 x 512B  w fragments (GEMM2 A operand)
#define SM_ZW   32768      // 64 x 132 x 4 = 33792
#define SM_GP   66560      // 2240
#define SM_BR   68800      // B ring: 4 stages x 6656B = 26624
#define SMEM_TOTAL 95424   // x2 CTAs = 191KB

// ---------------- main fused kernel (2 CTAs/SM) ----------------
extern "C" __global__ void __launch_bounds__(256, 2)
ks_main(float* __restrict__ out) {
    extern __shared__ __align__(128) char smem[];
    const unsigned sb = smem_u32(smem);
    const int tid = threadIdx.x, wid = tid >> 5, lane = tid & 31;
    const int g = lane >> 2, tig = lane & 3;
    const int r = blockIdx.y, tile = blockIdx.x, b0 = tile * MT;
    const int mw = wid >> 2, nw = wid & 3;
    const unsigned sxb = (unsigned)((g & 1) << 6);

    float* ZW  = (float*)(smem + SM_ZW);
    float* GP  = (float*)(smem + SM_GP);

    for (int i = tid; i < 560; i += 256) GP[i] = g_P[r * 560 + i];

    // ======== GEMM1: z[64][100] = x[64][256] @ Ucat ========
    // B via cp.async 4-stage smem ring; A via LDG with distance-2 register ring.
    {
        // producer chunk mapping: chunk c = tile*32+lane, c0 = tid, c1 = tid+256
        const int c0t = tid >> 5, c0l = tid & 31;
        const int c1 = tid + 256;
        const int c1t = c1 >> 5, c1l = c1 & 31;
        const bool hasC1 = (tid < 160);                  // 416 chunks total
        const uint4* U1r = (const uint4*)g_u1 + (size_t)r * 6656;   // 13*512

        #define ISSUE_STAGE(stg, kbi) do {                                        \
            CP16(sb + SM_BR + (stg) * 6656 + tid * 16,                            \
                 (const void*)(U1r + c0t * 512 + (kbi) * 32 + c0l));              \
            if (hasC1)                                                            \
                CP16(sb + SM_BR + (stg) * 6656 + c1 * 16,                         \
                     (const void*)(U1r + c1t * 512 + (kbi) * 32 + c1l));          \
        } while (0)

        ISSUE_STAGE(0, 0); CPCOMMIT();
        ISSUE_STAGE(1, 1); CPCOMMIT();
        ISSUE_STAGE(2, 2); CPCOMMIT();

        const uint4* XP = (const uint4*)g_xp + (size_t)tile * 4096
                        + (tig * 64 + mw * 32 + g);
        int tv[4];
        #pragma unroll
        for (int nt = 0; nt < 4; nt++) tv[nt] = (nw + 4 * nt) < 13;

        uint4 aa[2][2][2];
        #pragma unroll
        for (int p = 0; p < 2; p++)
            #pragma unroll
            for (int mt = 0; mt < 2; mt++)
                #pragma unroll
                for (int h = 0; h < 2; h++)
                    aa[p][mt][h] = XP[p * 256 + mt * 16 + 8 * h];

        float acc[2][4][4];
        #pragma unroll
        for (int mt = 0; mt < 2; mt++)
            #pragma unroll
            for (int nt = 0; nt < 4; nt++)
                #pragma unroll
                for (int q = 0; q < 4; q++) acc[mt][nt][q] = 0.0f;

        #pragma unroll
        for (int kb = 0; kb < 16; kb++) {
            CPWAIT2();
            __syncthreads();
            if (kb + 3 < 16) ISSUE_STAGE((kb + 3) & 3, kb + 3);
            CPCOMMIT();                                   // empty group ok for tail

            const uint4* Bst = (const uint4*)(smem + SM_BR + (kb & 3) * 6656);
            uint4 b[4];
            #pragma unroll
            for (int nt = 0; nt < 4; nt++)
                if (tv[nt]) b[nt] = Bst[(nw + 4 * nt) * 32 + lane];

            #pragma unroll
            for (int nt = 0; nt < 4; nt++) {
                if (!tv[nt]) continue;
                #pragma unroll
                for (int mt = 0; mt < 2; mt++) {
                    mma8(acc[mt][nt], aa[kb & 1][mt][0].x, aa[kb & 1][mt][1].x,
                         aa[kb & 1][mt][0].y, aa[kb & 1][mt][1].y, b[nt].x, b[nt].y);
                    mma8(acc[mt][nt], aa[kb & 1][mt][0].z, aa[kb & 1][mt][1].z,
                         aa[kb & 1][mt][0].w, aa[kb & 1][mt][1].w, b[nt].z, b[nt].w);
                }
            }
            if (kb + 2 < 16) {
                #pragma unroll
                for (int mt = 0; mt < 2; mt++)
                    #pragma unroll
                    for (int h = 0; h < 2; h++)
                        aa[kb & 1][mt][h] = XP[(kb + 2) * 256 + mt * 16 + 8 * h];
            }
        }
        #undef ISSUE_STAGE

        #pragma unroll
        for (int mt = 0; mt < 2; mt++)
            #pragma unroll
            for (int nt = 0; nt < 4; nt++)
                if (tv[nt]) {
                    const int col = (nw + 4 * nt) * 8 + 2 * tig;   // even
                    const int ks = col / 10, d = col - ks * 10;
                    const int r0 = mw * 32 + mt * 16 + g;
                    *(float2*)(ZW + r0 * ZSTR + ks * 12 + d) =
                        make_float2(acc[mt][nt][0], acc[mt][nt][1]);
                    *(float2*)(ZW + (r0 + 8) * ZSTR + ks * 12 + d) =
                        make_float2(acc[mt][nt][2], acc[mt][nt][3]);
                }
    }
    __syncthreads();

    // ======== merged: logits + softmax (quad shuffles) + w-pack ========
    {
        const int row = tid >> 2, sub = tid & 3;
        const int nk = (sub < 2) ? 3 : 2;        // k = sub, sub+4, sub+8(sub<2)
        const float* zR = ZW + row * ZSTR;

        float z[3][10], lg[3], ex[3];
        float m = -1e30f;
        #pragma unroll
        for (int i = 0; i < 3; i++) {
            if (i >= nk) continue;
            const int k = sub + 4 * i;
            const float4 z0 = *(const float4*)(zR + k * 12);
            const float4 z1 = *(const float4*)(zR + k * 12 + 4);
            const float2 z2 = *(const float2*)(zR + k * 12 + 8);
            z[i][0] = z0.x; z[i][1] = z0.y; z[i][2] = z0.z; z[i][3] = z0.w;
            z[i][4] = z1.x; z[i][5] = z1.y; z[i][6] = z1.z; z[i][7] = z1.w;
            z[i][8] = z2.x; z[i][9] = z2.y;
            float s1 = 0.0f;
            #pragma unroll
            for (int d = 0; d < DL_; d++) s1 += z[i][d] * z[i][d];
            const float* Pk = GP + k * 56;
            float s2 = 0.0f; int tt = 0;
            #pragma unroll
            for (int i2 = 0; i2 < DL_; i2++)
                #pragma unroll
                for (int j2 = i2; j2 < DL_; j2++) { s2 += Pk[tt] * z[i][i2] * z[i][j2]; tt++; }
            lg[i] = 10.0f * s1 - 5.0f * s2;
            m = fmaxf(m, lg[i]);
        }
        m = fmaxf(m, __shfl_xor_sync(0xffffffffu, m, 1));
        m = fmaxf(m, __shfl_xor_sync(0xffffffffu, m, 2));
        float s = 0.0f;
        #pragma unroll
        for (int i = 0; i < 3; i++)
            if (i < nk) { ex[i] = __expf(lg[i] - m); s += ex[i]; }
        s += __shfl_xor_sync(0xffffffffu, s, 1);
        s += __shfl_xor_sync(0xffffffffu, s, 2);
        const float inv = 1.0f / s;

        const unsigned wb = SM_W + row * 512;
        const unsigned x6 = ((unsigned)(row & 1)) << 6;
        #pragma unroll
        for (int i = 0; i < 3; i++) {
            if (i >= nk) continue;
            const int k = sub + 4 * i;
            const float c = ex[i] * inv;
            #pragma unroll
            for (int d = 0; d < DL_; d++) {
                const int j = k * 10 + d;
                *(unsigned*)(smem + wb + (((unsigned)(j * 4)) ^ x6)) = tf32b(c * z[i][d]);
            }
        }
        #pragma unroll
        for (int i = 0; i < 3; i++) {           // zero-pad cols 100..111
            const int jp = 100 + sub * 3 + i;
            *(unsigned*)(smem + wb + (((unsigned)(jp * 4)) ^ x6)) = 0u;
        }
    }
    __syncthreads();

    // ======== GEMM2: out[64][256] = w[64][112] @ Ucat^T ========
    float acc2[2][8][4];
    {
        #pragma unroll
        for (int mt = 0; mt < 2; mt++)
            #pragma unroll
            for (int nt = 0; nt < 8; nt++)
                #pragma unroll
                for (int q = 0; q < 4; q++) acc2[mt][nt][q] = 0.0f;

        const char* Ar[2][2];
        #pragma unroll
        for (int mt = 0; mt < 2; mt++)
            #pragma unroll
            for (int h = 0; h < 2; h++)
                Ar[mt][h] = smem + SM_W + (mw * 32 + mt * 16 + g + 8 * h) * 512;

        const uint4* U2 = (const uint4*)g_u2 + (size_t)r * (32 * 7 * 32)
                        + (nw * 8) * (7 * 32) + lane;

        #pragma unroll 2
        for (int kb = 0; kb < 7; kb++) {
            const unsigned ka = ((unsigned)(kb * 64 + tig * 16)) ^ sxb;
            uint4 a[2][2];
            #pragma unroll
            for (int mt = 0; mt < 2; mt++)
                #pragma unroll
                for (int h = 0; h < 2; h++)
                    a[mt][h] = *(const uint4*)(Ar[mt][h] + ka);
            #pragma unroll
            for (int nt = 0; nt < 8; nt++) {
                const uint4 b = U2[(nt * 7 + kb) * 32];
                #pragma unroll
                for (int mt = 0; mt < 2; mt++) {
                    mma8(acc2[mt][nt], a[mt][0].x, a[mt][1].x, a[mt][0].y, a[mt][1].y, b.x, b.y);
                    mma8(acc2[mt][nt], a[mt][0].z, a[mt][1].z, a[mt][0].w, a[mt][1].w, b.z, b.w);
                }
            }
        }
    }

    // ======== epilogue: direct STG.64 from fragments (32B chunks per quad) ========
    {
        float* op = out + ((size_t)r * B_ + b0) * D_;
        #pragma unroll
        for (int mt = 0; mt < 2; mt++) {
            const int r0 = mw * 32 + mt * 16 + g;
            #pragma unroll
            for (int nt = 0; nt < 8; nt++) {
                const int col = (nw * 8 + nt) * 8 + 2 * tig;
                *(float2*)(op + r0 * D_ + col) =
                    make_float2(acc2[mt][nt][0], acc2[mt][nt][1]);
                *(float2*)(op + (r0 + 8) * D_ + col) =
                    make_float2(acc2[mt][nt][2], acc2[mt][nt][3]);
            }
        }
    }
}

extern "C" void kernel_launch(void* const* d_in, const int* in_sizes, int n_in,
                              void* d_out, int out_size) {
    const float* x  = (const float*)d_in[0];   // (4096, 256)
    const float* Us = (const float*)d_in[1];   // (8, 10, 256, 10)
    float* out = (float*)d_out;                // (8, 4096, 256)

    cudaFuncSetAttribute(ks_main, cudaFuncAttributeMaxDynamicSharedMemorySize,
                         SMEM_TOTAL);

    ks_prep<<<696, 256>>>(x, Us);

    dim3 grid(NT_, R_);
    ks_main<<<grid, 256, SMEM_TOTAL>>>(out);
}

// round 13
// speedup vs baseline: 2.1899x; 2.1899x over previous
#include <cuda_runtime.h>
#include <cuda_fp16.h>

#define R_ 8
#define K_ 10
#define D_ 256
#define DL_ 10
#define B_ 4096
#define MT 64
#define NT_ 64          // number of row tiles = B_/MT
#define ZSTR 132        // k-slots of 12 floats, stride 132

// ---------------- device scratch (static, no allocs) ----------------
__device__ float    g_P[R_ * K_ * 56];            // packed symmetric Gram
__device__ unsigned g_xa[NT_ * 2048 * 4];         // x fp16 A-frags [tile][kb16][tig][blk][g] uint4 (2MB)
__device__ unsigned g_u1h[R_ * 13 * 16 * 32 * 2]; // GEMM1 B frags fp16 [r][t13][kb16][lane] uint2
__device__ unsigned g_u2h[R_ * 32 * 7 * 32 * 2];  // GEMM2 B frags fp16 [r][t32][kb7][lane] uint2

__device__ __forceinline__ unsigned h2u(float lo, float hi) {
    __half2 h = __floats2half2_rn(lo, hi);
    return *reinterpret_cast<unsigned*>(&h);
}
__device__ __forceinline__ void mma16(float* c, unsigned a0, unsigned a1,
                                      unsigned a2, unsigned a3,
                                      unsigned b0, unsigned b1) {
    asm volatile(
        "mma.sync.aligned.m16n8k16.row.col.f32.f16.f16.f32 "
        "{%0,%1,%2,%3}, {%4,%5,%6,%7}, {%8,%9}, {%0,%1,%2,%3};"
        : "+f"(c[0]), "+f"(c[1]), "+f"(c[2]), "+f"(c[3])
        : "r"(a0), "r"(a1), "r"(a2), "r"(a3), "r"(b0), "r"(b1));
}

// ---------------- fused prep kernel ----------------
// blocks [0,256):   xpack  tile = b>>2, quarter = b&3
// blocks [256,336): gram   rk   = b-256
// blocks [336,440): upack1 idx  = b-336  (r*13+t13)
// blocks [440,696): upack2 idx  = b-440  (r*32+t32)
__global__ void __launch_bounds__(256)
ks_prep(const float* __restrict__ x, const float* __restrict__ Us) {
    const int b = blockIdx.x, tidb = threadIdx.x;

    if (b < 256) {                      // ---- xpack: fp16 A fragments ----
        const int tile = b >> 2, q = b & 3;
        #pragma unroll
        for (int it = 0; it < 2; it++) {
            const int e = q * 512 + it * 256 + tidb;     // 0..2047
            const int g   = e & 7;
            const int blk = (e >> 3) & 3;
            const int tig = (e >> 5) & 3;
            const int kb  = e >> 7;
            const int rA = tile * 64 + blk * 16 + g;
            const int c0 = kb * 16 + tig * 2;
            const float* pA = x + (size_t)rA * D_ + c0;
            const float* pB = pA + 8 * D_;
            uint4 v;
            v.x = h2u(pA[0], pA[1]);
            v.y = h2u(pB[0], pB[1]);
            v.z = h2u(pA[8], pA[9]);
            v.w = h2u(pB[8], pB[9]);
            ((uint4*)g_xa)[(size_t)tile * 2048 + e] = v;
        }
    } else if (b < 336) {               // ---- gram ----
        __shared__ float u[D_ * DL_];
        __shared__ float G[DL_ * DL_];
        const int rk = b - 256;
        const float* Up = Us + (size_t)rk * D_ * DL_;
        for (int i = tidb; i < D_ * DL_; i += 256) u[i] = Up[i];
        __syncthreads();
        if (tidb < DL_ * DL_) {
            const int i = tidb / DL_, j = tidb % DL_;
            float s = 0.0f;
            #pragma unroll 8
            for (int dd = 0; dd < D_; dd++) s += u[dd * DL_ + i] * u[dd * DL_ + j];
            G[tidb] = s;
        }
        __syncthreads();
        if (tidb < 55) {
            int tt = tidb, i = 0;
            while (tt >= DL_ - i) { tt -= DL_ - i; i++; }
            const int j = i + tt;
            g_P[rk * 56 + tidb] = G[i * DL_ + j] * (i == j ? 1.0f : 2.0f);
        }
    } else if (b < 440) {               // ---- upack1 (fp16 B frags, GEMM1) ----
        const int idx = b - 336;
        const int r = idx / 13, t13 = idx % 13;
        for (int e = tidb; e < 512; e += 256) {
            const int lane = e & 31, kb = e >> 5;
            const int g = lane >> 2, tig = lane & 3;
            const int j = t13 * 8 + g;
            uint2 v = make_uint2(0u, 0u);
            if (j < 100) {
                const int k0 = kb * 16 + tig * 2;
                const float* up = Us + ((size_t)(r * 10 + j / 10) * D_) * 10 + (j % 10);
                v.x = h2u(up[(size_t)k0 * 10],       up[(size_t)(k0 + 1) * 10]);
                v.y = h2u(up[(size_t)(k0 + 8) * 10], up[(size_t)(k0 + 9) * 10]);
            }
            ((uint2*)g_u1h)[((r * 13 + t13) * 16 + kb) * 32 + lane] = v;
        }
    } else {                            // ---- upack2 (fp16 B frags, GEMM2) ----
        const int idx = b - 440;
        const int r = idx >> 5, t32 = idx & 31;
        if (tidb < 224) {
            const int lane = tidb & 31, kb = tidb >> 5;
            const int g = lane >> 2, tig = lane & 3;
            const int n = t32 * 8 + g;
            const int j0 = kb * 16 + tig * 2;
            float f[4];
            const int js[4] = {j0, j0 + 1, j0 + 8, j0 + 9};
            #pragma unroll
            for (int q = 0; q < 4; q++) {
                const int j = js[q];
                f[q] = (j < 100)
                    ? Us[((size_t)(r * 10 + j / 10) * D_ + n) * 10 + (j % 10)]
                    : 0.0f;
            }
            uint2 v;
            v.x = h2u(f[0], f[1]);
            v.y = h2u(f[2], f[3]);
            ((uint2*)g_u2h)[((r * 32 + t32) * 7 + kb) * 32 + lane] = v;
        }
    }
}

// ---------------- smem layout (bytes) ----------------
#define SM_W2   0          // W fp16 frags [blk4][h2][kb7][g8][tig4] uint2 = 14336
#define SM_ZW   14336      // 64 x 132 x 4 = 33792
#define SM_GP   48128      // 2240
#define SMEM_TOTAL 50368

// ---------------- main fused kernel (2 CTAs/SM) ----------------
extern "C" __global__ void __launch_bounds__(256, 2)
ks_main(float* __restrict__ out) {
    extern __shared__ __align__(128) char smem[];
    const int tid = threadIdx.x, wid = tid >> 5, lane = tid & 31;
    const int g = lane >> 2, tig = lane & 3;
    const int r = blockIdx.y, tile = blockIdx.x, b0 = tile * MT;
    const int mw = wid >> 2, nw = wid & 3;

    float* ZW  = (float*)(smem + SM_ZW);
    float* GP  = (float*)(smem + SM_GP);

    for (int i = tid; i < 560; i += 256) GP[i] = g_P[r * 560 + i];

    // ======== GEMM1: z[64][100] = x[64][256] @ Ucat  (fp16 m16n8k16) ========
    {
        const uint4* XP = (const uint4*)g_xa + (size_t)tile * 2048;
        const uint2* U1 = (const uint2*)g_u1h + (size_t)r * (13 * 16 * 32) + lane;
        int tv[4];
        #pragma unroll
        for (int nt = 0; nt < 4; nt++) tv[nt] = (nw + 4 * nt) < 13;

        float acc[2][4][4];
        #pragma unroll
        for (int mt = 0; mt < 2; mt++)
            #pragma unroll
            for (int nt = 0; nt < 4; nt++)
                #pragma unroll
                for (int q = 0; q < 4; q++) acc[mt][nt][q] = 0.0f;

        #pragma unroll
        for (int kb = 0; kb < 16; kb++) {
            uint4 a[2];
            #pragma unroll
            for (int mt = 0; mt < 2; mt++)
                a[mt] = XP[((kb * 4 + tig) * 4 + (mw * 2 + mt)) * 8 + g];
            uint2 bfr[4];
            #pragma unroll
            for (int nt = 0; nt < 4; nt++)
                if (tv[nt]) bfr[nt] = U1[((nw + 4 * nt) * 16 + kb) * 32];
            #pragma unroll
            for (int nt = 0; nt < 4; nt++) {
                if (!tv[nt]) continue;
                #pragma unroll
                for (int mt = 0; mt < 2; mt++)
                    mma16(acc[mt][nt], a[mt].x, a[mt].y, a[mt].z, a[mt].w,
                          bfr[nt].x, bfr[nt].y);
            }
        }
        #pragma unroll
        for (int mt = 0; mt < 2; mt++)
            #pragma unroll
            for (int nt = 0; nt < 4; nt++)
                if (tv[nt]) {
                    const int col = (nw + 4 * nt) * 8 + 2 * tig;   // even
                    const int ks = col / 10, d = col - ks * 10;
                    const int r0 = mw * 32 + mt * 16 + g;
                    *(float2*)(ZW + r0 * ZSTR + ks * 12 + d) =
                        make_float2(acc[mt][nt][0], acc[mt][nt][1]);
                    *(float2*)(ZW + (r0 + 8) * ZSTR + ks * 12 + d) =
                        make_float2(acc[mt][nt][2], acc[mt][nt][3]);
                }
    }
    __syncthreads();

    // ======== merged: logits + softmax (quad shuffles) + fp16 w-frag pack ========
    {
        const int row = tid >> 2, sub = tid & 3;
        const int nk = (sub < 2) ? 3 : 2;        // k = sub, sub+4, sub+8(sub<2)
        const float* zR = ZW + row * ZSTR;
        const int blk = row >> 4, hh = (row >> 3) & 1, gg = row & 7;

        float z[3][10], lg[3], ex[3];
        float m = -1e30f;
        #pragma unroll
        for (int i = 0; i < 3; i++) {
            if (i >= nk) continue;
            const int k = sub + 4 * i;
            const float4 z0 = *(const float4*)(zR + k * 12);
            const float4 z1 = *(const float4*)(zR + k * 12 + 4);
            const float2 z2 = *(const float2*)(zR + k * 12 + 8);
            z[i][0] = z0.x; z[i][1] = z0.y; z[i][2] = z0.z; z[i][3] = z0.w;
            z[i][4] = z1.x; z[i][5] = z1.y; z[i][6] = z1.z; z[i][7] = z1.w;
            z[i][8] = z2.x; z[i][9] = z2.y;
            float s1 = 0.0f;
            #pragma unroll
            for (int d = 0; d < DL_; d++) s1 += z[i][d] * z[i][d];
            const float* Pk = GP + k * 56;
            float s2 = 0.0f; int tt = 0;
            #pragma unroll
            for (int i2 = 0; i2 < DL_; i2++)
                #pragma unroll
                for (int j2 = i2; j2 < DL_; j2++) { s2 += Pk[tt] * z[i][i2] * z[i][j2]; tt++; }
            lg[i] = 10.0f * s1 - 5.0f * s2;
            m = fmaxf(m, lg[i]);
        }
        m = fmaxf(m, __shfl_xor_sync(0xffffffffu, m, 1));
        m = fmaxf(m, __shfl_xor_sync(0xffffffffu, m, 2));
        float s = 0.0f;
        #pragma unroll
        for (int i = 0; i < 3; i++)
            if (i < nk) { ex[i] = __expf(lg[i] - m); s += ex[i]; }
        s += __shfl_xor_sync(0xffffffffu, s, 1);
        s += __shfl_xor_sync(0xffffffffu, s, 2);
        const float inv = 1.0f / s;

        // write w = c*z as fp16 into lane-linear frag layout
        #pragma unroll
        for (int i = 0; i < 3; i++) {
            if (i >= nk) continue;
            const int k = sub + 4 * i;
            const float c = ex[i] * inv;
            #pragma unroll
            for (int d = 0; d < DL_; d++) {
                const int j = k * 10 + d;
                const int kb = j >> 4, c2 = j & 15;
                const int tg = (c2 & 7) >> 1, sel = c2 >> 3, w1 = c2 & 1;
                const unsigned addr = SM_W2 +
                    ((((blk * 2 + hh) * 7 + kb) * 32 + gg * 4 + tg) << 3) +
                    sel * 4 + w1 * 2;
                *(__half*)(smem + addr) = __float2half_rn(c * z[i][d]);
            }
        }
        #pragma unroll
        for (int i = 0; i < 3; i++) {           // zero-pad j = 100..111
            const int j = 100 + sub * 3 + i;
            const int kb = j >> 4, c2 = j & 15;
            const int tg = (c2 & 7) >> 1, sel = c2 >> 3, w1 = c2 & 1;
            const unsigned addr = SM_W2 +
                ((((blk * 2 + hh) * 7 + kb) * 32 + gg * 4 + tg) << 3) +
                sel * 4 + w1 * 2;
            *(__half*)(smem + addr) = __float2half_rn(0.0f);
        }
    }
    __syncthreads();

    // ======== GEMM2: out[64][256] = w[64][112] @ Ucat^T  (fp16 m16n8k16) ========
    float acc2[2][8][4];
    {
        #pragma unroll
        for (int mt = 0; mt < 2; mt++)
            #pragma unroll
            for (int nt = 0; nt < 8; nt++)
                #pragma unroll
                for (int q = 0; q < 4; q++) acc2[mt][nt][q] = 0.0f;

        const uint2* WF = (const uint2*)(smem + SM_W2);
        const uint2* U2 = (const uint2*)g_u2h + (size_t)r * (32 * 7 * 32)
                        + (nw * 8) * (7 * 32) + lane;

        #pragma unroll
        for (int kb = 0; kb < 7; kb++) {
            uint2 ah[2][2];
            #pragma unroll
            for (int mt = 0; mt < 2; mt++)
                #pragma unroll
                for (int h = 0; h < 2; h++)
                    ah[mt][h] = WF[(((mw * 2 + mt) * 2 + h) * 7 + kb) * 32 + g * 4 + tig];
            #pragma unroll
            for (int nt = 0; nt < 8; nt++) {
                const uint2 b = U2[(nt * 7 + kb) * 32];
                #pragma unroll
                for (int mt = 0; mt < 2; mt++)
                    mma16(acc2[mt][nt], ah[mt][0].x, ah[mt][1].x,
                          ah[mt][0].y, ah[mt][1].y, b.x, b.y);
            }
        }
    }

    // ======== epilogue: direct STG.64 from fragments (32B chunks per quad) ========
    {
        float* op = out + ((size_t)r * B_ + b0) * D_;
        #pragma unroll
        for (int mt = 0; mt < 2; mt++) {
            const int r0 = mw * 32 + mt * 16 + g;
            #pragma unroll
            for (int nt = 0; nt < 8; nt++) {
                const int col = (nw * 8 + nt) * 8 + 2 * tig;
                *(float2*)(op + r0 * D_ + col) =
                    make_float2(acc2[mt][nt][0], acc2[mt][nt][1]);
                *(float2*)(op + (r0 + 8) * D_ + col) =
                    make_float2(acc2[mt][nt][2], acc2[mt][nt][3]);
            }
        }
    }
}

extern "C" void kernel_launch(void* const* d_in, const int* in_sizes, int n_in,
                              void* d_out, int out_size) {
    const float* x  = (const float*)d_in[0];   // (4096, 256)
    const float* Us = (const float*)d_in[1];   // (8, 10, 256, 10)
    float* out = (float*)d_out;                // (8, 4096, 256)

    cudaFuncSetAttribute(ks_main, cudaFuncAttributeMaxDynamicSharedMemorySize,
                         SMEM_TOTAL);

    ks_prep<<<696, 256>>>(x, Us);

    dim3 grid(NT_, R_);
    ks_main<<<grid, 256, SMEM_TOTAL>>>(out);
}

// round 14
// speedup vs baseline: 2.5343x; 1.1573x over previous
#include <cuda_runtime.h>
#include <cuda_fp16.h>

#define R_ 8
#define K_ 10
#define D_ 256
#define DL_ 10
#define B_ 4096
#define MT 64
#define NT_ 64          // number of row tiles = B_/MT
#define ZSTR 132        // k-slots of 12 floats, stride 132

// ---------------- device scratch (static, no allocs) ----------------
__device__ float    g_P[R_ * K_ * 56];            // packed symmetric Gram
__device__ unsigned g_xa[NT_ * 2048 * 4];         // x fp16 A-frags [tile][kb16][blk4][lane32] uint4 (2MB)
__device__ unsigned g_u1h[R_ * 13 * 16 * 32 * 2]; // GEMM1 B frags fp16 [r][t13][kb16][lane] uint2
__device__ unsigned g_u2h[R_ * 32 * 7 * 32 * 2];  // GEMM2 B frags fp16 [r][t32][kb7][lane] uint2

__device__ __forceinline__ unsigned h2u(float lo, float hi) {
    __half2 h = __floats2half2_rn(lo, hi);
    return *reinterpret_cast<unsigned*>(&h);
}
__device__ __forceinline__ void mma16(float* c, unsigned a0, unsigned a1,
                                      unsigned a2, unsigned a3,
                                      unsigned b0, unsigned b1) {
    asm volatile(
        "mma.sync.aligned.m16n8k16.row.col.f32.f16.f16.f32 "
        "{%0,%1,%2,%3}, {%4,%5,%6,%7}, {%8,%9}, {%0,%1,%2,%3};"
        : "+f"(c[0]), "+f"(c[1]), "+f"(c[2]), "+f"(c[3])
        : "r"(a0), "r"(a1), "r"(a2), "r"(a3), "r"(b0), "r"(b1));
}

// ---------------- fused prep kernel ----------------
// blocks [0,256):   xpack  tile = b>>2, quarter = b&3
// blocks [256,336): gram   rk   = b-256
// blocks [336,440): upack1 idx  = b-336  (r*13+t13)
// blocks [440,696): upack2 idx  = b-440  (r*32+t32)
__global__ void __launch_bounds__(256)
ks_prep(const float* __restrict__ x, const float* __restrict__ Us) {
    const int b = blockIdx.x, tidb = threadIdx.x;

    if (b < 256) {                      // ---- xpack: fp16 A fragments [kb][blk][lane] ----
        const int tile = b >> 2, q = b & 3;
        #pragma unroll
        for (int it = 0; it < 2; it++) {
            const int e = q * 512 + it * 256 + tidb;     // 0..2047
            const int lane = e & 31;
            const int blk  = (e >> 5) & 3;
            const int kb   = e >> 7;
            const int tig = lane & 3, g = lane >> 2;
            const int rA = tile * 64 + blk * 16 + g;
            const int c0 = kb * 16 + tig * 2;
            const float* pA = x + (size_t)rA * D_ + c0;
            const float* pB = pA + 8 * D_;
            uint4 v;
            v.x = h2u(pA[0], pA[1]);
            v.y = h2u(pB[0], pB[1]);
            v.z = h2u(pA[8], pA[9]);
            v.w = h2u(pB[8], pB[9]);
            ((uint4*)g_xa)[(size_t)tile * 2048 + e] = v;
        }
    } else if (b < 336) {               // ---- gram ----
        __shared__ float u[D_ * DL_];
        __shared__ float G[DL_ * DL_];
        const int rk = b - 256;
        const float* Up = Us + (size_t)rk * D_ * DL_;
        for (int i = tidb; i < D_ * DL_; i += 256) u[i] = Up[i];
        __syncthreads();
        if (tidb < DL_ * DL_) {
            const int i = tidb / DL_, j = tidb % DL_;
            float s = 0.0f;
            #pragma unroll 8
            for (int dd = 0; dd < D_; dd++) s += u[dd * DL_ + i] * u[dd * DL_ + j];
            G[tidb] = s;
        }
        __syncthreads();
        if (tidb < 55) {
            int tt = tidb, i = 0;
            while (tt >= DL_ - i) { tt -= DL_ - i; i++; }
            const int j = i + tt;
            g_P[rk * 56 + tidb] = G[i * DL_ + j] * (i == j ? 1.0f : 2.0f);
        }
    } else if (b < 440) {               // ---- upack1 (fp16 B frags, GEMM1) ----
        const int idx = b - 336;
        const int r = idx / 13, t13 = idx % 13;
        for (int e = tidb; e < 512; e += 256) {
            const int lane = e & 31, kb = e >> 5;
            const int g = lane >> 2, tig = lane & 3;
            const int j = t13 * 8 + g;
            uint2 v = make_uint2(0u, 0u);
            if (j < 100) {
                const int k0 = kb * 16 + tig * 2;
                const float* up = Us + ((size_t)(r * 10 + j / 10) * D_) * 10 + (j % 10);
                v.x = h2u(up[(size_t)k0 * 10],       up[(size_t)(k0 + 1) * 10]);
                v.y = h2u(up[(size_t)(k0 + 8) * 10], up[(size_t)(k0 + 9) * 10]);
            }
            ((uint2*)g_u1h)[((r * 13 + t13) * 16 + kb) * 32 + lane] = v;
        }
    } else {                            // ---- upack2 (fp16 B frags, GEMM2) ----
        const int idx = b - 440;
        const int r = idx >> 5, t32 = idx & 31;
        if (tidb < 224) {
            const int lane = tidb & 31, kb = tidb >> 5;
            const int g = lane >> 2, tig = lane & 3;
            const int n = t32 * 8 + g;
            const int j0 = kb * 16 + tig * 2;
            float f[4];
            const int js[4] = {j0, j0 + 1, j0 + 8, j0 + 9};
            #pragma unroll
            for (int q = 0; q < 4; q++) {
                const int j = js[q];
                f[q] = (j < 100)
                    ? Us[((size_t)(r * 10 + j / 10) * D_ + n) * 10 + (j % 10)]
                    : 0.0f;
            }
            uint2 v;
            v.x = h2u(f[0], f[1]);
            v.y = h2u(f[2], f[3]);
            ((uint2*)g_u2h)[((r * 32 + t32) * 7 + kb) * 32 + lane] = v;
        }
    }
}

// ---------------- smem layout (bytes) ----------------
// Phase A (staging + GEMM1 reads): SA 0..32768, SB 32768..86016
// Phase B (after barrier):         ZW 0..33792, W2 33792..48128
#define SM_STA  0          // A stage: 2048 uint4 = 32768
#define SM_STB  32768      // B1 stage: 6656 uint2 = 53248
#define SM_ZW   0          // overlay: 64 x 132 x 4 = 33792
#define SM_W2   33792      // overlay: W fp16 frags = 14336
#define SM_GP   86016      // 2240
#define SMEM_TOTAL 88256   // x2 CTAs = 176.5 KB

// ---------------- main fused kernel (2 CTAs/SM) ----------------
extern "C" __global__ void __launch_bounds__(256, 2)
ks_main(float* __restrict__ out) {
    extern __shared__ __align__(128) char smem[];
    const int tid = threadIdx.x, wid = tid >> 5, lane = tid & 31;
    const int g = lane >> 2, tig = lane & 3;
    const int r = blockIdx.y, tile = blockIdx.x, b0 = tile * MT;
    const int mw = wid >> 2, nw = wid & 3;

    float* ZW  = (float*)(smem + SM_ZW);
    float* GP  = (float*)(smem + SM_GP);

    for (int i = tid; i < 560; i += 256) GP[i] = g_P[r * 560 + i];

    // ======== stage GEMM1 operands: flat LDG.128 -> STS.128 burst ========
    {
        const uint4* XAs = (const uint4*)g_xa + (size_t)tile * 2048;
        uint4* SA = (uint4*)(smem + SM_STA);
        #pragma unroll
        for (int it = 0; it < 8; it++) SA[it * 256 + tid] = XAs[it * 256 + tid];
        const uint4* U1s = (const uint4*)g_u1h + (size_t)r * 3328;
        uint4* SB = (uint4*)(smem + SM_STB);
        #pragma unroll
        for (int it = 0; it < 13; it++) SB[it * 256 + tid] = U1s[it * 256 + tid];
    }
    __syncthreads();

    // ======== GEMM1: z[64][100] = x[64][256] @ Ucat  (all-smem operands) ========
    float acc[2][4][4];
    int tv[4];
    {
        const uint4* SA4 = (const uint4*)(smem + SM_STA);
        const uint2* SB2 = (const uint2*)(smem + SM_STB);
        #pragma unroll
        for (int nt = 0; nt < 4; nt++) tv[nt] = (nw + 4 * nt) < 13;

        #pragma unroll
        for (int mt = 0; mt < 2; mt++)
            #pragma unroll
            for (int nt = 0; nt < 4; nt++)
                #pragma unroll
                for (int q = 0; q < 4; q++) acc[mt][nt][q] = 0.0f;

        #pragma unroll
        for (int kb = 0; kb < 16; kb++) {
            uint4 a[2];
            #pragma unroll
            for (int mt = 0; mt < 2; mt++)
                a[mt] = SA4[(kb * 4 + mw * 2 + mt) * 32 + lane];
            uint2 bfr[4];
            #pragma unroll
            for (int nt = 0; nt < 4; nt++)
                if (tv[nt]) bfr[nt] = SB2[((nw + 4 * nt) * 16 + kb) * 32 + lane];
            #pragma unroll
            for (int nt = 0; nt < 4; nt++) {
                if (!tv[nt]) continue;
                #pragma unroll
                for (int mt = 0; mt < 2; mt++)
                    mma16(acc[mt][nt], a[mt].x, a[mt].y, a[mt].z, a[mt].w,
                          bfr[nt].x, bfr[nt].y);
            }
        }
    }
    __syncthreads();   // all stage reads done; region becomes ZW + W2

    // ======== ZW fragment stores (into overlay region) ========
    #pragma unroll
    for (int mt = 0; mt < 2; mt++)
        #pragma unroll
        for (int nt = 0; nt < 4; nt++)
            if (tv[nt]) {
                const int col = (nw + 4 * nt) * 8 + 2 * tig;   // even
                const int ks = col / 10, d = col - ks * 10;
                const int r0 = mw * 32 + mt * 16 + g;
                *(float2*)(ZW + r0 * ZSTR + ks * 12 + d) =
                    make_float2(acc[mt][nt][0], acc[mt][nt][1]);
                *(float2*)(ZW + (r0 + 8) * ZSTR + ks * 12 + d) =
                    make_float2(acc[mt][nt][2], acc[mt][nt][3]);
            }
    __syncthreads();

    // ======== merged: logits + softmax (quad shuffles) + fp16 w-frag pack ========
    {
        const int row = tid >> 2, sub = tid & 3;
        const int nk = (sub < 2) ? 3 : 2;        // k = sub, sub+4, sub+8(sub<2)
        const float* zR = ZW + row * ZSTR;
        const int blk = row >> 4, hh = (row >> 3) & 1, gg = row & 7;

        float z[3][10], lg[3], ex[3];
        float m = -1e30f;
        #pragma unroll
        for (int i = 0; i < 3; i++) {
            if (i >= nk) continue;
            const int k = sub + 4 * i;
            const float4 z0 = *(const float4*)(zR + k * 12);
            const float4 z1 = *(const float4*)(zR + k * 12 + 4);
            const float2 z2 = *(const float2*)(zR + k * 12 + 8);
            z[i][0] = z0.x; z[i][1] = z0.y; z[i][2] = z0.z; z[i][3] = z0.w;
            z[i][4] = z1.x; z[i][5] = z1.y; z[i][6] = z1.z; z[i][7] = z1.w;
            z[i][8] = z2.x; z[i][9] = z2.y;
            float s1 = 0.0f;
            #pragma unroll
            for (int d = 0; d < DL_; d++) s1 += z[i][d] * z[i][d];
            const float* Pk = GP + k * 56;
            float s2 = 0.0f; int tt = 0;
            #pragma unroll
            for (int i2 = 0; i2 < DL_; i2++)
                #pragma unroll
                for (int j2 = i2; j2 < DL_; j2++) { s2 += Pk[tt] * z[i][i2] * z[i][j2]; tt++; }
            lg[i] = 10.0f * s1 - 5.0f * s2;
            m = fmaxf(m, lg[i]);
        }
        m = fmaxf(m, __shfl_xor_sync(0xffffffffu, m, 1));
        m = fmaxf(m, __shfl_xor_sync(0xffffffffu, m, 2));
        float s = 0.0f;
        #pragma unroll
        for (int i = 0; i < 3; i++)
            if (i < nk) { ex[i] = __expf(lg[i] - m); s += ex[i]; }
        s += __shfl_xor_sync(0xffffffffu, s, 1);
        s += __shfl_xor_sync(0xffffffffu, s, 2);
        const float inv = 1.0f / s;

        // write w = c*z as fp16 into lane-linear frag layout
        #pragma unroll
        for (int i = 0; i < 3; i++) {
            if (i >= nk) continue;
            const int k = sub + 4 * i;
            const float c = ex[i] * inv;
            #pragma unroll
            for (int d = 0; d < DL_; d++) {
                const int j = k * 10 + d;
                const int kb = j >> 4, c2 = j & 15;
                const int tg = (c2 & 7) >> 1, sel = c2 >> 3, w1 = c2 & 1;
                const unsigned addr = SM_W2 +
                    ((((blk * 2 + hh) * 7 + kb) * 32 + gg * 4 + tg) << 3) +
                    sel * 4 + w1 * 2;
                *(__half*)(smem + addr) = __float2half_rn(c * z[i][d]);
            }
        }
        #pragma unroll
        for (int i = 0; i < 3; i++) {           // zero-pad j = 100..111
            const int j = 100 + sub * 3 + i;
            const int kb = j >> 4, c2 = j & 15;
            const int tg = (c2 & 7) >> 1, sel = c2 >> 3, w1 = c2 & 1;
            const unsigned addr = SM_W2 +
                ((((blk * 2 + hh) * 7 + kb) * 32 + gg * 4 + tg) << 3) +
                sel * 4 + w1 * 2;
            *(__half*)(smem + addr) = __float2half_rn(0.0f);
        }
    }
    __syncthreads();

    // ======== GEMM2: out[64][256] = w[64][112] @ Ucat^T  (fp16 m16n8k16) ========
    float acc2[2][8][4];
    {
        #pragma unroll
        for (int mt = 0; mt < 2; mt++)
            #pragma unroll
            for (int nt = 0; nt < 8; nt++)
                #pragma unroll
                for (int q = 0; q < 4; q++) acc2[mt][nt][q] = 0.0f;

        const uint2* WF = (const uint2*)(smem + SM_W2);
        const uint2* U2 = (const uint2*)g_u2h + (size_t)r * (32 * 7 * 32)
                        + (nw * 8) * (7 * 32) + lane;

        #pragma unroll
        for (int kb = 0; kb < 7; kb++) {
            uint2 ah[2][2];
            #pragma unroll
            for (int mt = 0; mt < 2; mt++)
                #pragma unroll
                for (int h = 0; h < 2; h++)
                    ah[mt][h] = WF[(((mw * 2 + mt) * 2 + h) * 7 + kb) * 32 + g * 4 + tig];
            #pragma unroll
            for (int nt = 0; nt < 8; nt++) {
                const uint2 b = U2[(nt * 7 + kb) * 32];
                #pragma unroll
                for (int mt = 0; mt < 2; mt++)
                    mma16(acc2[mt][nt], ah[mt][0].x, ah[mt][1].x,
                          ah[mt][0].y, ah[mt][1].y, b.x, b.y);
            }
        }
    }

    // ======== epilogue: direct STG.64 from fragments (32B chunks per quad) ========
    {
        float* op = out + ((size_t)r * B_ + b0) * D_;
        #pragma unroll
        for (int mt = 0; mt < 2; mt++) {
            const int r0 = mw * 32 + mt * 16 + g;
            #pragma unroll
            for (int nt = 0; nt < 8; nt++) {
                const int col = (nw * 8 + nt) * 8 + 2 * tig;
                *(float2*)(op + r0 * D_ + col) =
                    make_float2(acc2[mt][nt][0], acc2[mt][nt][1]);
                *(float2*)(op + (r0 + 8) * D_ + col) =
                    make_float2(acc2[mt][nt][2], acc2[mt][nt][3]);
            }
        }
    }
}

extern "C" void kernel_launch(void* const* d_in, const int* in_sizes, int n_in,
                              void* d_out, int out_size) {
    const float* x  = (const float*)d_in[0];   // (4096, 256)
    const float* Us = (const float*)d_in[1];   // (8, 10, 256, 10)
    float* out = (float*)d_out;                // (8, 4096, 256)

    cudaFuncSetAttribute(ks_main, cudaFuncAttributeMaxDynamicSharedMemorySize,
                         SMEM_TOTAL);

    ks_prep<<<696, 256>>>(x, Us);

    dim3 grid(NT_, R_);
    ks_main<<<grid, 256, SMEM_TOTAL>>>(out);
}